// round 8
// baseline (speedup 1.0000x reference)
#include <cuda_runtime.h>

#define Bn 8
#define Cn 32
#define Hn 512
#define Wn 512
#define On 4
#define TW 64
#define TH 32
#define RR 4
#define SST 68          // smem row stride (floats), even -> 8B-aligned pairs
#define NTHREADS 256
#define BN_EPS 1e-5f

typedef unsigned long long ull;

__device__ double g_stats[2 * On];   // [0..3] sum, [4..7] sumsq
__device__ float  g_scale[On];
__device__ float  g_bias[On];

__device__ __forceinline__ void fma2(ull& d, ull a, ull b) {
    // per-lane fp32 fma on packed f32x2 (sm_100+): d = a*b + d
    asm("fma.rn.f32x2 %0, %1, %2, %0;" : "+l"(d) : "l"(a), "l"(b));
}
__device__ __forceinline__ ull splat2(float f) {
    unsigned u = __float_as_uint(f);
    return ((ull)u << 32) | (ull)u;
}
__device__ __forceinline__ float2 unpack2(ull v) {
    float2 r;
    r.x = __uint_as_float((unsigned)v);
    r.y = __uint_as_float((unsigned)(v >> 32));
    return r;
}

__global__ void zero_stats_kernel() {
    if (threadIdx.x < 2 * On) g_stats[threadIdx.x] = 0.0;
}

// ---------------------------------------------------------------------------
// Pass 1: fused 5-tap stencil "conv" (4C->4 1x1 over 4 directional diffs),
// writes y into d_out and accumulates per-channel sum/sumsq for BN.
// ---------------------------------------------------------------------------
__global__ __launch_bounds__(NTHREADS, 2)
void fourdir_main(const float* __restrict__ x,
                  const float* __restrict__ wc_g,
                  float* __restrict__ out)
{
    __shared__ __align__(16) float sx[(TH + 2) * SST];
    __shared__ ull   swt[Cn][5][On];   // splatted weights: dirs NE,NW,SE,SW,C
    __shared__ float s_red[2 * On];

    const int tid = threadIdx.x;
    const int bxw = blockIdx.x;   // w tile (8)
    const int byh = blockIdx.y;   // h tile (16)
    const int bz  = blockIdx.z;   // batch (8)

    // Build combined weights once per block (tid < 128 covers all (c,o))
    if (tid < Cn * On) {
        int c = tid >> 2, o = tid & 3;
        float w0 = wc_g[o * (4 * Cn) + 0 * Cn + c];  // NE
        float w1 = wc_g[o * (4 * Cn) + 1 * Cn + c];  // NW
        float w2 = wc_g[o * (4 * Cn) + 2 * Cn + c];  // SE
        float w3 = wc_g[o * (4 * Cn) + 3 * Cn + c];  // SW
        swt[c][0][o] = splat2(w0);
        swt[c][1][o] = splat2(w1);
        swt[c][2][o] = splat2(w2);
        swt[c][3][o] = splat2(w3);
        swt[c][4][o] = splat2(-(w0 + w1 + w2 + w3)); // center
    }
    if (tid < 2 * On) s_red[tid] = 0.0f;

    const int px = tid & 31;       // pair-column index (32 pairs = 64 cols)
    const int gy = tid >> 5;       // row group (8 groups x RR rows = 32 rows)
    const int lw = px << 1;        // local output col (even)
    const int i0 = gy * RR;        // first output row (local)

    const int gh0 = byh * TH - 1;  // global row of smem row 0 (halo)
    const int gw0 = bxw * TW - 1;  // global col of smem col 0 (halo)

    ull acc[RR][On];
#pragma unroll
    for (int r2 = 0; r2 < RR; ++r2)
#pragma unroll
        for (int o = 0; o < On; ++o) acc[r2][o] = 0ull;

    const int wi = tid >> 5, ln = tid & 31;
    const int base = i0 * SST + lw;

    for (int c = 0; c < Cn; ++c) {
        __syncthreads();  // previous channel's compute done (and init visible)

        // stage x[b, c, gh0..gh0+33, gw0..gw0+65] with zero halo
        const float* xc = x + ((size_t)(bz * Cn + c)) * (Hn * Wn);
        for (int r = wi; r < TH + 2; r += NTHREADS / 32) {
            int gh = gh0 + r;
            bool hok = (unsigned)gh < (unsigned)Hn;
            const float* xr = xc + (size_t)gh * Wn;
            for (int col = ln; col < TW + 2; col += 32) {
                int gw = gw0 + col;
                float v = (hok && (unsigned)gw < (unsigned)Wn) ? __ldg(xr + gw) : 0.0f;
                sx[r * SST + col] = v;
            }
        }
        __syncthreads();

        const ull* wp = &swt[c][0][0];

        // rolling rows: A = (x[w-1],x[w]) pair, B = (x[w+1],x[w+2]) pair
        ull Au = *(const ull*)(sx + base);
        ull Bu = *(const ull*)(sx + base + 2);
        ull Am = *(const ull*)(sx + base + SST);
        ull Bm = *(const ull*)(sx + base + SST + 2);
#pragma unroll
        for (int r2 = 0; r2 < RR; ++r2) {
            const float* rp = sx + base + (r2 + 2) * SST;
            ull Ad = *(const ull*)rp;
            ull Bd = *(const ull*)(rp + 2);
            ull Cm = (Am >> 32) | (Bm << 32);   // (x[w], x[w+1]) center pair
#pragma unroll
            for (int o = 0; o < On; ++o) {
                fma2(acc[r2][o], wp[0 * On + o], Bu);  // NE: x(h-1, w+1..w+2)
                fma2(acc[r2][o], wp[1 * On + o], Au);  // NW: x(h-1, w-1..w)
                fma2(acc[r2][o], wp[2 * On + o], Bd);  // SE: x(h+1, w+1..w+2)
                fma2(acc[r2][o], wp[3 * On + o], Ad);  // SW: x(h+1, w-1..w)
                fma2(acc[r2][o], wp[4 * On + o], Cm);  // C : x(h,   w..w+1)
            }
            Au = Am; Bu = Bm; Am = Ad; Bm = Bd;
        }
    }

    // epilogue: write y, accumulate BN stats
    float s[On] = {0, 0, 0, 0}, q[On] = {0, 0, 0, 0};
    const int wcol = bxw * TW + lw;
#pragma unroll
    for (int r2 = 0; r2 < RR; ++r2) {
        int h = byh * TH + i0 + r2;
#pragma unroll
        for (int o = 0; o < On; ++o) {
            float2 y = unpack2(acc[r2][o]);
            *(float2*)(out + (((size_t)(bz * On + o)) * Hn + h) * Wn + wcol) = y;
            s[o] += y.x + y.y;
            q[o] += y.x * y.x + y.y * y.y;
        }
    }
#pragma unroll
    for (int o = 0; o < On; ++o) {
        for (int off = 16; off; off >>= 1) {
            s[o] += __shfl_xor_sync(0xffffffffu, s[o], off);
            q[o] += __shfl_xor_sync(0xffffffffu, q[o], off);
        }
    }
    if ((tid & 31) == 0) {
#pragma unroll
        for (int o = 0; o < On; ++o) {
            atomicAdd(&s_red[o], s[o]);
            atomicAdd(&s_red[On + o], q[o]);
        }
    }
    __syncthreads();
    if (tid < 2 * On) atomicAdd(&g_stats[tid], (double)s_red[tid]);
}

// ---------------------------------------------------------------------------
// Pass 2: finalize BN scale/bias (tiny)
// ---------------------------------------------------------------------------
__global__ void finalize_stats(const float* __restrict__ gamma,
                               const float* __restrict__ beta)
{
    int o = threadIdx.x;
    if (o < On) {
        const double N = (double)Bn * Hn * Wn;
        double mean = g_stats[o] / N;
        double var  = g_stats[On + o] / N - mean * mean;
        float sc = gamma[o] * (float)(1.0 / sqrt(var + (double)BN_EPS));
        g_scale[o] = sc;
        g_bias[o]  = beta[o] - (float)mean * sc;
    }
}

// ---------------------------------------------------------------------------
// Pass 3: normalize d_out in place (vectorized)
// ---------------------------------------------------------------------------
__global__ void apply_bn(float4* __restrict__ y)
{
    int i = blockIdx.x * blockDim.x + threadIdx.x;  // 2,097,152 float4s
    int c = (i >> 16) & 3;                          // H*W/4 = 65536 float4 per plane
    float sc = g_scale[c], bi = g_bias[c];
    float4 v = y[i];
    v.x = v.x * sc + bi;
    v.y = v.y * sc + bi;
    v.z = v.z * sc + bi;
    v.w = v.w * sc + bi;
    y[i] = v;
}

extern "C" void kernel_launch(void* const* d_in, const int* in_sizes, int n_in,
                              void* d_out, int out_size)
{
    const float* x     = (const float*)d_in[0];
    const float* w     = (const float*)d_in[1];
    const float* gamma = (const float*)d_in[2];
    const float* beta  = (const float*)d_in[3];
    float* out = (float*)d_out;

    zero_stats_kernel<<<1, 32>>>();

    dim3 grid(Wn / TW, Hn / TH, Bn);   // (8, 16, 8) = 1024 blocks
    fourdir_main<<<grid, NTHREADS>>>(x, w, out);

    finalize_stats<<<1, 32>>>(gamma, beta);

    int n4 = Bn * On * Hn * Wn / 4;    // 2,097,152
    apply_bn<<<n4 / 256, 256>>>((float4*)out);
}

// round 9
// speedup vs baseline: 5.4657x; 5.4657x over previous
#include <cuda_runtime.h>

#define Bn 8
#define Cn 32
#define Hn 512
#define Wn 512
#define On 4
#define TW 64
#define TH 32
#define RR 4
#define SST 66                  // smem row stride (floats), even -> 8B-aligned pairs
#define SROWS (TH + 2)
#define SN (SROWS * SST)        // 2244 floats staged per channel
#define K_LD 9                  // ceil(2244 / 256)
#define NTHREADS 256
#define BN_EPS 1e-5f

__device__ double g_stats[2 * On];   // [0..3] sum, [4..7] sumsq
__device__ float  g_scale[On];
__device__ float  g_bias[On];

__global__ void zero_stats_kernel() {
    if (threadIdx.x < 2 * On) g_stats[threadIdx.x] = 0.0;
}

// ---------------------------------------------------------------------------
// Pass 1: fused 5-tap stencil (4 directional diffs -> 1x1 conv 4C->4),
// scalar fp32 engine, register-prefetch double buffering of the x tile.
// ---------------------------------------------------------------------------
__global__ __launch_bounds__(NTHREADS, 2)
void fourdir_main(const float* __restrict__ x,
                  const float* __restrict__ wc_g,
                  float* __restrict__ out)
{
    __shared__ __align__(16) float sx[SN];
    __shared__ __align__(16) float swt[Cn][5][On];  // taps: NE,NW,SE,SW,C ; o contiguous
    __shared__ float s_red[2 * On];

    const int tid = threadIdx.x;
    const int bxw = blockIdx.x;   // w tile (8)
    const int byh = blockIdx.y;   // h tile (16)
    const int bz  = blockIdx.z;   // batch (8)

    // Build combined weights once per block (tid < 128 covers all (c,o))
    if (tid < Cn * On) {
        int c = tid >> 2, o = tid & 3;
        float w0 = wc_g[o * (4 * Cn) + 0 * Cn + c];  // NE
        float w1 = wc_g[o * (4 * Cn) + 1 * Cn + c];  // NW
        float w2 = wc_g[o * (4 * Cn) + 2 * Cn + c];  // SE
        float w3 = wc_g[o * (4 * Cn) + 3 * Cn + c];  // SW
        swt[c][0][o] = w0;
        swt[c][1][o] = w1;
        swt[c][2][o] = w2;
        swt[c][3][o] = w3;
        swt[c][4][o] = -(w0 + w1 + w2 + w3);         // center tap
    }
    if (tid < 2 * On) s_red[tid] = 0.0f;

    const int px = tid & 31;       // pair-column index (32 pairs = 64 cols)
    const int gy = tid >> 5;       // row group (8 groups x RR rows = 32 rows)
    const int lw = px << 1;        // local output col (even)
    const int i0 = gy * RR;        // first output row (local)

    const int gh0 = byh * TH - 1;  // global row of smem row 0 (halo)
    const int gw0 = bxw * TW - 1;  // global col of smem col 0 (halo)

    // Precompute staging offsets (loop-invariant across channels)
    int off[K_LD];
#pragma unroll
    for (int k = 0; k < K_LD; ++k) {
        int i = tid + k * NTHREADS;
        int r = i / SST;
        int cl = i - r * SST;
        int gh = gh0 + r;
        int gw = gw0 + cl;
        bool ok = (i < SN) && ((unsigned)gh < (unsigned)Hn) && ((unsigned)gw < (unsigned)Wn);
        off[k] = ok ? (gh * Wn + gw) : -1;
    }

    const float* xb = x + (size_t)bz * Cn * Hn * Wn;

    // Prefetch channel 0 into registers
    float v[K_LD];
#pragma unroll
    for (int k = 0; k < K_LD; ++k)
        v[k] = (off[k] >= 0) ? __ldg(xb + off[k]) : 0.0f;

    float acc[RR][On][2];
#pragma unroll
    for (int r2 = 0; r2 < RR; ++r2)
#pragma unroll
        for (int o = 0; o < On; ++o) { acc[r2][o][0] = 0.0f; acc[r2][o][1] = 0.0f; }

    const float* bp0 = sx + i0 * SST + lw;

    for (int c = 0; c < Cn; ++c) {
        __syncthreads();   // previous channel's compute done (smem reusable)

        // publish current channel's tile
#pragma unroll
        for (int k = 0; k < K_LD; ++k) {
            int i = tid + k * NTHREADS;
            if (i < SN) sx[i] = v[k];
        }

        // prefetch next channel (last iteration re-reads same plane; values unused)
        {
            int cn = (c < Cn - 1) ? (c + 1) : c;
            const float* xn = xb + (size_t)cn * (Hn * Wn);
#pragma unroll
            for (int k = 0; k < K_LD; ++k)
                v[k] = (off[k] >= 0) ? __ldg(xn + off[k]) : 0.0f;
        }

        __syncthreads();   // staging visible

        // broadcast weight loads: 5 x LDS.128
        float4 wNE = *(const float4*)&swt[c][0][0];
        float4 wNW = *(const float4*)&swt[c][1][0];
        float4 wSE = *(const float4*)&swt[c][2][0];
        float4 wSW = *(const float4*)&swt[c][3][0];
        float4 wCC = *(const float4*)&swt[c][4][0];
        const float* wne = &wNE.x;
        const float* wnw = &wNW.x;
        const float* wse = &wSE.x;
        const float* wsw = &wSW.x;
        const float* wcc = &wCC.x;

        // rolling rows; A = smem cols (lw, lw+1) = global (w-1, w); B = (w+1, w+2)
        float2 uA = *(const float2*)(bp0);
        float2 uB = *(const float2*)(bp0 + 2);
        float2 mA = *(const float2*)(bp0 + SST);
        float2 mB = *(const float2*)(bp0 + SST + 2);
#pragma unroll
        for (int r2 = 0; r2 < RR; ++r2) {
            const float* rp = bp0 + (r2 + 2) * SST;
            float2 dA = *(const float2*)(rp);
            float2 dB = *(const float2*)(rp + 2);
#pragma unroll
            for (int o = 0; o < On; ++o) {
                // output col w   : NE=uB.x NW=uA.x SE=dB.x SW=dA.x C=mA.y
                float a0 = acc[r2][o][0];
                a0 += wne[o] * uB.x;
                a0 += wnw[o] * uA.x;
                a0 += wse[o] * dB.x;
                a0 += wsw[o] * dA.x;
                a0 += wcc[o] * mA.y;
                acc[r2][o][0] = a0;
                // output col w+1 : NE=uB.y NW=uA.y SE=dB.y SW=dA.y C=mB.x
                float a1 = acc[r2][o][1];
                a1 += wne[o] * uB.y;
                a1 += wnw[o] * uA.y;
                a1 += wse[o] * dB.y;
                a1 += wsw[o] * dA.y;
                a1 += wcc[o] * mB.x;
                acc[r2][o][1] = a1;
            }
            uA = mA; uB = mB; mA = dA; mB = dB;
        }
    }

    // epilogue: write y, accumulate BN stats
    float s[On] = {0, 0, 0, 0}, q[On] = {0, 0, 0, 0};
    const int wcol = bxw * TW + lw;
#pragma unroll
    for (int r2 = 0; r2 < RR; ++r2) {
        int h = byh * TH + i0 + r2;
#pragma unroll
        for (int o = 0; o < On; ++o) {
            float2 y;
            y.x = acc[r2][o][0];
            y.y = acc[r2][o][1];
            *(float2*)(out + (((size_t)(bz * On + o)) * Hn + h) * Wn + wcol) = y;
            s[o] += y.x + y.y;
            q[o] += y.x * y.x + y.y * y.y;
        }
    }
#pragma unroll
    for (int o = 0; o < On; ++o) {
        for (int offs = 16; offs; offs >>= 1) {
            s[o] += __shfl_xor_sync(0xffffffffu, s[o], offs);
            q[o] += __shfl_xor_sync(0xffffffffu, q[o], offs);
        }
    }
    if ((tid & 31) == 0) {
#pragma unroll
        for (int o = 0; o < On; ++o) {
            atomicAdd(&s_red[o], s[o]);
            atomicAdd(&s_red[On + o], q[o]);
        }
    }
    __syncthreads();
    if (tid < 2 * On) atomicAdd(&g_stats[tid], (double)s_red[tid]);
}

// ---------------------------------------------------------------------------
// Pass 2: finalize BN scale/bias (tiny)
// ---------------------------------------------------------------------------
__global__ void finalize_stats(const float* __restrict__ gamma,
                               const float* __restrict__ beta)
{
    int o = threadIdx.x;
    if (o < On) {
        const double N = (double)Bn * Hn * Wn;
        double mean = g_stats[o] / N;
        double var  = g_stats[On + o] / N - mean * mean;
        float sc = gamma[o] * (float)(1.0 / sqrt(var + (double)BN_EPS));
        g_scale[o] = sc;
        g_bias[o]  = beta[o] - (float)mean * sc;
    }
}

// ---------------------------------------------------------------------------
// Pass 3: normalize d_out in place (vectorized)
// ---------------------------------------------------------------------------
__global__ void apply_bn(float4* __restrict__ y)
{
    int i = blockIdx.x * blockDim.x + threadIdx.x;  // 2,097,152 float4s
    int c = (i >> 16) & 3;                          // H*W/4 = 65536 float4 per plane
    float sc = g_scale[c], bi = g_bias[c];
    float4 v = y[i];
    v.x = v.x * sc + bi;
    v.y = v.y * sc + bi;
    v.z = v.z * sc + bi;
    v.w = v.w * sc + bi;
    y[i] = v;
}

extern "C" void kernel_launch(void* const* d_in, const int* in_sizes, int n_in,
                              void* d_out, int out_size)
{
    const float* x     = (const float*)d_in[0];
    const float* w     = (const float*)d_in[1];
    const float* gamma = (const float*)d_in[2];
    const float* beta  = (const float*)d_in[3];
    float* out = (float*)d_out;

    zero_stats_kernel<<<1, 32>>>();

    dim3 grid(Wn / TW, Hn / TH, Bn);   // (8, 16, 8) = 1024 blocks
    fourdir_main<<<grid, NTHREADS>>>(x, w, out);

    finalize_stats<<<1, 32>>>(gamma, beta);

    int n4 = Bn * On * Hn * Wn / 4;    // 2,097,152
    apply_bn<<<n4 / 256, 256>>>((float4*)out);
}